// round 2
// baseline (speedup 1.0000x reference)
#include <cuda_runtime.h>
#include <stdint.h>

#define BB 8
#define NN 50000
#define CC 80
#define KK 500            // per-class candidate cap
#define MAXD 300          // max detections
#define CAP 16384         // per-class compacted-candidate capacity (mean ~8560, sigma ~84)
#define FLATCAP (CC*MAXD) // 24000 max kept per image

typedef unsigned long long u64;
typedef unsigned int u32;

// ---------------- device scratch ----------------
__device__ u64 g_list[(size_t)BB * CC * CAP];  // per-(b,c) compacted (key<<32 | n)
__device__ int g_cnt[BB * CC];
__device__ u32 g_cand_key[BB * CC * KK];
__device__ int g_cand_idx[BB * CC * KK];
__device__ u64 g_kept[BB * FLATCAP];           // per-image kept (key<<32 | c*KK+k)
__device__ int g_kcnt[BB];

// ---------------- K0: zero counters (graph replays need fresh state) ----------------
__global__ void k_zero() {
    for (int i = threadIdx.x; i < BB * CC; i += blockDim.x) g_cnt[i] = 0;
    if (threadIdx.x < BB) g_kcnt[threadIdx.x] = 0;
}

// ---------------- K1: fused threshold + compact ----------------
// classification [B,N,C] scanned once; s>0.05 appended to per-(b,c) list.
__global__ void k_compact(const float4* __restrict__ cls4) {
    const int TOT4 = BB * NN * CC / 4;
    int stride = gridDim.x * blockDim.x;
    for (int q = blockIdx.x * blockDim.x + threadIdx.x; q < TOT4; q += stride) {
        float4 v = cls4[q];
        int e0 = q * 4;
        float sv[4] = {v.x, v.y, v.z, v.w};
        #pragma unroll
        for (int j = 0; j < 4; j++) {
            float s = sv[j];
            if (s > 0.05f) {
                int e = e0 + j;
                int c = e % CC;
                int r = e / CC;
                int n = r % NN;
                int b = r / NN;
                int bc = b * CC + c;
                int pos = atomicAdd(&g_cnt[bc], 1);
                if (pos < CAP)
                    g_list[(size_t)bc * CAP + pos] =
                        ((u64)__float_as_uint(s) << 32) | (u32)n;
            }
        }
    }
}

// ---------------- shared helpers: exact radix select + gather/sort ----------------
// Returns the rem-th largest key (0 if fewer than rem entries). Block-uniform.
__device__ u32 radix_select_key(const u64* __restrict__ list, int m, int rem_init) {
    if (m <= rem_init) return 0u;   // uniform early-out: take everything
    __shared__ u32 hist[256];
    __shared__ u32 s_prefix, s_maskhi, s_rem;
    int tid = threadIdx.x, T = blockDim.x, lane = tid & 31;
    if (tid == 0) { s_prefix = 0u; s_maskhi = 0u; s_rem = (u32)rem_init; }
    __syncthreads();
    int mp = (m + T - 1) / T * T;   // padded so all warps run identical trips
    for (int p = 0; p < 4; p++) {
        int shift = 24 - 8 * p;
        for (int i = tid; i < 256; i += T) hist[i] = 0u;
        __syncthreads();
        u32 pf = s_prefix, mh = s_maskhi;
        for (int i = tid; i < mp; i += T) {
            bool ok = i < m;
            u32 k = ok ? (u32)(list[i] >> 32) : 0u;
            ok = ok && ((k & mh) == pf);
            u32 bin = ok ? ((k >> shift) & 255u) : 0xFFFFFFFFu;
            u32 peers = __match_any_sync(0xffffffffu, bin);
            if (ok && lane == (__ffs(peers) - 1))
                atomicAdd(&hist[bin], (u32)__popc(peers));
        }
        __syncthreads();
        if (tid == 0) {
            u32 rem = s_rem, cum = 0u; int chosen = 0;
            for (int bn = 255; bn >= 0; bn--) {
                u32 c2 = cum + hist[bn];
                if (c2 >= rem) { chosen = bn; break; }
                cum = c2;
            }
            s_rem = rem - cum;
            s_prefix = pf | ((u32)chosen << shift);
            s_maskhi = mh | (255u << shift);
        }
        __syncthreads();
    }
    return s_prefix;
}

// Gather (> Tkey) plus capped ties (== Tkey), bitonic sort 1024 on (key desc, idx asc).
__device__ void gather_sort(const u64* __restrict__ list, int m, u32 Tkey, u64* ent) {
    __shared__ int s_g, s_e;
    int tid = threadIdx.x, T = blockDim.x;
    if (tid == 0) { s_g = 0; s_e = 0; }
    for (int i = tid; i < 1024; i += T) ent[i] = 0ull;
    __syncthreads();
    for (int i = tid; i < m; i += T) {
        u64 v = list[i];
        u32 k = (u32)(v >> 32);
        u32 id = (u32)v;
        if (k > Tkey) {
            int p = atomicAdd(&s_g, 1);
            if (p < 512) ent[p] = ((u64)k << 32) | (u32)(~id);
        } else if (k == Tkey && k != 0u) {
            int p = atomicAdd(&s_e, 1);
            if (p < 512) ent[512 + p] = ((u64)k << 32) | (u32)(~id);
        }
    }
    __syncthreads();
    for (int kk = 2; kk <= 1024; kk <<= 1) {
        for (int j = kk >> 1; j > 0; j >>= 1) {
            for (int i = tid; i < 1024; i += T) {
                int ixj = i ^ j;
                if (ixj > i) {
                    u64 a = ent[i], b2 = ent[ixj];
                    bool up = ((i & kk) == 0);
                    if (up ? (a < b2) : (a > b2)) { ent[i] = b2; ent[ixj] = a; }
                }
            }
            __syncthreads();
        }
    }
}

// ---------------- K2: exact top-500 per (b,c) ----------------
__global__ void k_select() {
    __shared__ u64 ent[1024];
    int bc = blockIdx.x;
    int m = min(g_cnt[bc], CAP);
    const u64* list = g_list + (size_t)bc * CAP;
    u32 Tkey = radix_select_key(list, m, KK);
    gather_sort(list, m, Tkey, ent);
    for (int s = threadIdx.x; s < KK; s += blockDim.x) {
        u64 e = ent[s];
        g_cand_key[bc * KK + s] = (u32)(e >> 32);
        g_cand_idx[bc * KK + s] = (int)(~(u32)e);
    }
}

// ---------------- K3: greedy NMS per (b,c), append kept to per-image list ----------------
__global__ void k_nms(const float* __restrict__ boxes) {
    const int T = 256;
    int bc = blockIdx.x;
    int b = bc / CC;
    int c = bc % CC;
    __shared__ float4 sbox[KK];
    __shared__ float  sarea[KK];
    __shared__ u32    skey[KK];
    __shared__ u32    mask[KK][16];
    __shared__ u32    keepw[16];
    __shared__ int    kbase[16];
    int tid = threadIdx.x;
    const float* bx = boxes + (size_t)b * NN * 4;

    for (int k = tid; k < KK; k += T) {
        u32 key = g_cand_key[bc * KK + k];
        skey[k] = key;
        float4 bb = make_float4(0.f, 0.f, 0.f, 0.f);
        if (key) {
            int idx = g_cand_idx[bc * KK + k];
            bb = *reinterpret_cast<const float4*>(bx + (size_t)idx * 4);
        }
        sbox[k] = bb;
        sarea[k] = fmaxf(bb.z - bb.x, 0.f) * fmaxf(bb.w - bb.y, 0.f);
    }
    __syncthreads();

    for (int r = tid; r < KK; r += T) {
        float4 bi = sbox[r]; float ai = sarea[r];
        u32 m[16];
        #pragma unroll
        for (int w = 0; w < 16; w++) m[w] = 0u;
        for (int j = r + 1; j < KK; j++) {
            float4 bj = sbox[j];
            float yy1 = fmaxf(bi.x, bj.x), xx1 = fmaxf(bi.y, bj.y);
            float yy2 = fminf(bi.z, bj.z), xx2 = fminf(bi.w, bj.w);
            float inter = fmaxf(yy2 - yy1, 0.f) * fmaxf(xx2 - xx1, 0.f);
            float iou = inter / (ai + sarea[j] - inter + 1e-9f);
            if (iou > 0.5f) m[j >> 5] |= 1u << (j & 31);
        }
        #pragma unroll
        for (int w = 0; w < 16; w++) mask[r][w] = m[w];
    }
    __syncthreads();

    if (tid < 32) {
        int lane = tid;
        u32 sup = 0u, kw = 0u;
        for (int i = 0; i < KK; i++) {
            int w = i >> 5, bb2 = i & 31;
            u32 supw = __shfl_sync(0xffffffffu, sup, w);
            bool kept = (skey[i] != 0u) && !((supw >> bb2) & 1u);
            if (kept) {
                if (lane < 16) sup |= mask[i][lane];
                if (lane == w) kw |= 1u << bb2;
            }
        }
        if (lane < 16) keepw[lane] = kw;
        int cnt = (lane < 16) ? __popc(kw) : 0;
        int v = cnt;
        for (int off = 1; off < 32; off <<= 1) {
            int t2 = __shfl_up_sync(0xffffffffu, v, off);
            if (lane >= off) v += t2;
        }
        if (lane < 16) kbase[lane] = v - cnt;
    }
    __syncthreads();

    for (int k = tid; k < KK; k += T) {
        int w = k >> 5, bb2 = k & 31;
        u32 kwv = keepw[w];
        bool kept = (kwv >> bb2) & 1u;
        int rank = kbase[w] + __popc(kwv & ((1u << bb2) - 1u));
        kept = kept && (rank < MAXD);
        if (kept) {
            int pos = atomicAdd(&g_kcnt[b], 1);
            if (pos < FLATCAP)
                g_kept[b * FLATCAP + pos] =
                    ((u64)skey[k] << 32) | (u32)(c * KK + k);
        }
    }
}

// ---------------- K4: global top-300 per image + output ----------------
__global__ void k_final(const float* __restrict__ boxes, float* __restrict__ out) {
    __shared__ u64 ent[1024];
    int b = blockIdx.x;
    int m = min(g_kcnt[b], FLATCAP);
    const u64* list = g_kept + b * FLATCAP;
    u32 Tkey = radix_select_key(list, m, MAXD);
    gather_sort(list, m, Tkey, ent);

    float* oB = out;
    float* oS = out + (size_t)BB * MAXD * 4;
    float* oL = out + (size_t)BB * MAXD * 4 + (size_t)BB * MAXD;
    const float* bx = boxes + (size_t)b * NN * 4;
    for (int s = threadIdx.x; s < MAXD; s += blockDim.x) {
        u64 e = ent[s];
        u32 key = (u32)(e >> 32);
        float4 bb; float sc, lb;
        if (key) {
            u32 fidx = ~(u32)e;                 // flat index into [C*K]
            int c = (int)(fidx / KK);
            int k = (int)(fidx % KK);
            int idx = g_cand_idx[(b * CC + c) * KK + k];
            bb = *reinterpret_cast<const float4*>(bx + (size_t)idx * 4);
            sc = __uint_as_float(key);
            lb = (float)c;
        } else {
            bb = make_float4(-1.f, -1.f, -1.f, -1.f);
            sc = -1.f; lb = -1.f;
        }
        size_t row = (size_t)b * MAXD + s;
        oB[row * 4 + 0] = bb.x; oB[row * 4 + 1] = bb.y;
        oB[row * 4 + 2] = bb.z; oB[row * 4 + 3] = bb.w;
        oS[row] = sc;
        oL[row] = lb;
    }
}

// ---------------- launch ----------------
extern "C" void kernel_launch(void* const* d_in, const int* in_sizes, int n_in,
                              void* d_out, int out_size) {
    const float* boxes = (const float*)d_in[0];   // [8,50000,4]
    const float* cls   = (const float*)d_in[1];   // [8,50000,80]
    (void)in_sizes; (void)n_in; (void)out_size;

    k_zero<<<1, 256>>>();
    k_compact<<<4096, 256>>>((const float4*)cls);
    k_select<<<BB * CC, 256>>>();
    k_nms<<<BB * CC, 256>>>(boxes);
    k_final<<<BB, 512>>>(boxes, (float*)d_out);
}

// round 3
// speedup vs baseline: 3.3896x; 3.3896x over previous
#include <cuda_runtime.h>
#include <stdint.h>

#define BB 8
#define NN 50000
#define CC 80
#define KK 500            // per-class candidate cap
#define MAXD 300          // max detections
#define CAP 16384         // per-class compacted capacity (mean ~8.5K)
#define FLATCAP (CC*MAXD) // 24000 max kept per image
#define ROWS 250          // rows per compact block
#define NCHUNK (NN/ROWS)  // 200 chunks per image

typedef unsigned long long u64;
typedef unsigned int u32;

// ---------------- device scratch ----------------
__device__ u64 g_list[(size_t)BB * CC * CAP];  // per-(b,c) compacted (key<<32 | n)
__device__ int g_cnt[BB * CC];
__device__ u32 g_cand_key[BB * CC * KK];
__device__ int g_cand_idx[BB * CC * KK];
__device__ u64 g_kept[BB * FLATCAP];           // per-image kept (key<<32 | c*KK+k)
__device__ int g_kcnt[BB];

// ---------------- K0: zero counters ----------------
__global__ void k_zero() {
    for (int i = threadIdx.x; i < BB * CC; i += blockDim.x) g_cnt[i] = 0;
    if (threadIdx.x < BB) g_kcnt[threadIdx.x] = 0;
}

// ---------------- K1: reserve-then-write compaction ----------------
// Block owns ROWS rows (all C classes) of one image. Pass A: smem per-class
// counts; one global atomicAdd per (block,class) reserves a contiguous run.
// Pass B: re-read (L2-warm), write coalesced runs.
__global__ void k_compact(const float4* __restrict__ cls4) {
    __shared__ int s_cnt[CC];
    __shared__ int s_base[CC];
    const int T = blockDim.x;
    int tid = threadIdx.x;
    int b = blockIdx.x / NCHUNK;
    int chunk = blockIdx.x % NCHUNK;
    int row0 = chunk * ROWS;
    const float4* src = cls4 + ((size_t)b * NN + row0) * CC / 4;
    const int Q = ROWS * CC / 4;  // 5000 float4

    for (int c = tid; c < CC; c += T) s_cnt[c] = 0;
    __syncthreads();

    // Pass A: count
    for (int q = tid; q < Q; q += T) {
        float4 v = src[q];
        int e0 = q * 4;
        float sv[4] = {v.x, v.y, v.z, v.w};
        #pragma unroll
        for (int j = 0; j < 4; j++)
            if (sv[j] > 0.05f) atomicAdd(&s_cnt[(e0 + j) % CC], 1);
    }
    __syncthreads();

    // Reserve global runs; reset cursors
    for (int c = tid; c < CC; c += T) {
        s_base[c] = atomicAdd(&g_cnt[b * CC + c], s_cnt[c]);
        s_cnt[c] = 0;
    }
    __syncthreads();

    // Pass B: write
    for (int q = tid; q < Q; q += T) {
        float4 v = src[q];
        int e0 = q * 4;
        float sv[4] = {v.x, v.y, v.z, v.w};
        #pragma unroll
        for (int j = 0; j < 4; j++) {
            float s = sv[j];
            if (s > 0.05f) {
                int e = e0 + j;
                int c = e % CC;
                int n = row0 + e / CC;
                int slot = s_base[c] + atomicAdd(&s_cnt[c], 1);
                if (slot < CAP)
                    g_list[(size_t)(b * CC + c) * CAP + slot] =
                        ((u64)__float_as_uint(s) << 32) | (u32)n;
            }
        }
    }
}

// ---------------- radix select helper ----------------
// Returns the rem-th largest key (0 if fewer than rem entries). Block-uniform.
__device__ u32 radix_select_key(const u64* __restrict__ list, int m, int rem_init) {
    if (m <= rem_init) return 0u;
    __shared__ u32 hist[256];
    __shared__ u32 s_prefix, s_maskhi, s_rem;
    int tid = threadIdx.x, T = blockDim.x, lane = tid & 31;
    if (tid == 0) { s_prefix = 0u; s_maskhi = 0u; s_rem = (u32)rem_init; }
    __syncthreads();
    int mp = (m + T - 1) / T * T;
    for (int p = 0; p < 4; p++) {
        int shift = 24 - 8 * p;
        for (int i = tid; i < 256; i += T) hist[i] = 0u;
        __syncthreads();
        u32 pf = s_prefix, mh = s_maskhi;
        for (int i = tid; i < mp; i += T) {
            bool ok = i < m;
            u32 k = ok ? (u32)(list[i] >> 32) : 0u;
            ok = ok && ((k & mh) == pf);
            u32 bin = ok ? ((k >> shift) & 255u) : 0xFFFFFFFFu;
            u32 peers = __match_any_sync(0xffffffffu, bin);
            if (ok && lane == (__ffs(peers) - 1))
                atomicAdd(&hist[bin], (u32)__popc(peers));
        }
        __syncthreads();
        if (tid == 0) {
            u32 rem = s_rem, cum = 0u; int chosen = 0;
            for (int bn = 255; bn >= 0; bn--) {
                u32 c2 = cum + hist[bn];
                if (c2 >= rem) { chosen = bn; break; }
                cum = c2;
            }
            s_rem = rem - cum;
            s_prefix = pf | ((u32)chosen << shift);
            s_maskhi = mh | (255u << shift);
        }
        __syncthreads();
    }
    return s_prefix;
}

// Gather (> Tkey) plus capped ties, bitonic sort 1024 on (key desc, idx asc).
__device__ void gather_sort(const u64* __restrict__ list, int m, u32 Tkey, u64* ent) {
    __shared__ int s_g, s_e;
    int tid = threadIdx.x, T = blockDim.x;
    if (tid == 0) { s_g = 0; s_e = 0; }
    for (int i = tid; i < 1024; i += T) ent[i] = 0ull;
    __syncthreads();
    for (int i = tid; i < m; i += T) {
        u64 v = list[i];
        u32 k = (u32)(v >> 32);
        u32 id = (u32)v;
        if (k > Tkey) {
            int p = atomicAdd(&s_g, 1);
            if (p < 512) ent[p] = ((u64)k << 32) | (u32)(~id);
        } else if (k == Tkey && k != 0u) {
            int p = atomicAdd(&s_e, 1);
            if (p < 512) ent[512 + p] = ((u64)k << 32) | (u32)(~id);
        }
    }
    __syncthreads();
    for (int kk = 2; kk <= 1024; kk <<= 1) {
        for (int j = kk >> 1; j > 0; j >>= 1) {
            for (int i = tid; i < 1024; i += T) {
                int ixj = i ^ j;
                if (ixj > i) {
                    u64 a = ent[i], b2 = ent[ixj];
                    bool up = ((i & kk) == 0);
                    if (up ? (a < b2) : (a > b2)) { ent[i] = b2; ent[ixj] = a; }
                }
            }
            __syncthreads();
        }
    }
}

// ---------------- K2: exact top-500 per (b,c) ----------------
__global__ void k_select() {
    __shared__ u64 ent[1024];
    int bc = blockIdx.x;
    int m = min(g_cnt[bc], CAP);
    const u64* list = g_list + (size_t)bc * CAP;
    u32 Tkey = radix_select_key(list, m, KK);
    gather_sort(list, m, Tkey, ent);
    for (int s = threadIdx.x; s < KK; s += blockDim.x) {
        u64 e = ent[s];
        g_cand_key[bc * KK + s] = (u32)(e >> 32);
        g_cand_idx[bc * KK + s] = (int)(~(u32)e);
    }
}

// ---------------- K3: greedy NMS per (b,c) ----------------
__global__ void k_nms(const float* __restrict__ boxes) {
    const int T = 256;
    int bc = blockIdx.x;
    int b = bc / CC;
    int c = bc % CC;
    __shared__ float4 sbox[KK];
    __shared__ float  sarea[KK];
    __shared__ u32    skey[KK];
    __shared__ u32    mask[KK][16];
    __shared__ u32    keepw[16];
    __shared__ int    kbase[16];
    int tid = threadIdx.x;
    const float* bx = boxes + (size_t)b * NN * 4;

    for (int k = tid; k < KK; k += T) {
        u32 key = g_cand_key[bc * KK + k];
        skey[k] = key;
        float4 bb = make_float4(0.f, 0.f, 0.f, 0.f);
        if (key) {
            int idx = g_cand_idx[bc * KK + k];
            bb = *reinterpret_cast<const float4*>(bx + (size_t)idx * 4);
        }
        sbox[k] = bb;
        sarea[k] = fmaxf(bb.z - bb.x, 0.f) * fmaxf(bb.w - bb.y, 0.f);
    }
    __syncthreads();

    // pairwise IoU mask: build each 32-bit word in a register (no local array),
    // divide only when boxes actually intersect.
    for (int r = tid; r < KK; r += T) {
        float4 bi = sbox[r]; float ai = sarea[r];
        for (int w = 0; w < 16; w++) {
            int jbase = w << 5;
            u32 bits = 0u;
            if (jbase + 31 > r) {
                #pragma unroll 4
                for (int jj = 0; jj < 32; jj++) {
                    int j = jbase + jj;
                    if (j > r && j < KK) {
                        float4 bj = sbox[j];
                        float ih = fminf(bi.z, bj.z) - fmaxf(bi.x, bj.x);
                        float iw = fminf(bi.w, bj.w) - fmaxf(bi.y, bj.y);
                        if (ih > 0.f && iw > 0.f) {
                            float inter = ih * iw;
                            float iou = inter / (ai + sarea[j] - inter + 1e-9f);
                            if (iou > 0.5f) bits |= 1u << jj;
                        }
                    }
                }
            }
            mask[r][w] = bits;
        }
    }
    __syncthreads();

    // warp-cooperative greedy sweep
    if (tid < 32) {
        int lane = tid;
        u32 sup = 0u, kw = 0u;
        for (int i = 0; i < KK; i++) {
            int w = i >> 5, bb2 = i & 31;
            u32 supw = __shfl_sync(0xffffffffu, sup, w);
            bool kept = (skey[i] != 0u) && !((supw >> bb2) & 1u);
            if (kept) {
                if (lane < 16) sup |= mask[i][lane];
                if (lane == w) kw |= 1u << bb2;
            }
        }
        if (lane < 16) keepw[lane] = kw;
        int cnt = (lane < 16) ? __popc(kw) : 0;
        int v = cnt;
        for (int off = 1; off < 32; off <<= 1) {
            int t2 = __shfl_up_sync(0xffffffffu, v, off);
            if (lane >= off) v += t2;
        }
        if (lane < 16) kbase[lane] = v - cnt;
    }
    __syncthreads();

    // apply keep + cumsum<=300 cap; append kept to per-image list
    for (int k = tid; k < KK; k += T) {
        int w = k >> 5, bb2 = k & 31;
        u32 kwv = keepw[w];
        bool kept = (kwv >> bb2) & 1u;
        int rank = kbase[w] + __popc(kwv & ((1u << bb2) - 1u));
        kept = kept && (rank < MAXD);
        if (kept) {
            int pos = atomicAdd(&g_kcnt[b], 1);
            if (pos < FLATCAP)
                g_kept[b * FLATCAP + pos] =
                    ((u64)skey[k] << 32) | (u32)(c * KK + k);
        }
    }
}

// ---------------- K4: global top-300 per image + output ----------------
__global__ void k_final(const float* __restrict__ boxes, float* __restrict__ out) {
    __shared__ u64 ent[1024];
    int b = blockIdx.x;
    int m = min(g_kcnt[b], FLATCAP);
    const u64* list = g_kept + b * FLATCAP;
    u32 Tkey = radix_select_key(list, m, MAXD);
    gather_sort(list, m, Tkey, ent);

    float* oB = out;
    float* oS = out + (size_t)BB * MAXD * 4;
    float* oL = out + (size_t)BB * MAXD * 4 + (size_t)BB * MAXD;
    const float* bx = boxes + (size_t)b * NN * 4;
    for (int s = threadIdx.x; s < MAXD; s += blockDim.x) {
        u64 e = ent[s];
        u32 key = (u32)(e >> 32);
        float4 bb; float sc, lb;
        if (key) {
            u32 fidx = ~(u32)e;
            int c = (int)(fidx / KK);
            int k = (int)(fidx % KK);
            int idx = g_cand_idx[(b * CC + c) * KK + k];
            bb = *reinterpret_cast<const float4*>(bx + (size_t)idx * 4);
            sc = __uint_as_float(key);
            lb = (float)c;
        } else {
            bb = make_float4(-1.f, -1.f, -1.f, -1.f);
            sc = -1.f; lb = -1.f;
        }
        size_t row = (size_t)b * MAXD + s;
        oB[row * 4 + 0] = bb.x; oB[row * 4 + 1] = bb.y;
        oB[row * 4 + 2] = bb.z; oB[row * 4 + 3] = bb.w;
        oS[row] = sc;
        oL[row] = lb;
    }
}

// ---------------- launch ----------------
extern "C" void kernel_launch(void* const* d_in, const int* in_sizes, int n_in,
                              void* d_out, int out_size) {
    const float* boxes = (const float*)d_in[0];   // [8,50000,4]
    const float* cls   = (const float*)d_in[1];   // [8,50000,80]
    (void)in_sizes; (void)n_in; (void)out_size;

    k_zero<<<1, 256>>>();
    k_compact<<<BB * NCHUNK, 256>>>((const float4*)cls);
    k_select<<<BB * CC, 256>>>();
    k_nms<<<BB * CC, 256>>>(boxes);
    k_final<<<BB, 512>>>(boxes, (float*)d_out);
}